// round 15
// baseline (speedup 1.0000x reference)
#include <cuda_runtime.h>
#include <cuda_bf16.h>
#include <math.h>
#include <stdint.h>

// Problem shapes (fixed by setup_inputs): B=2, L=2048, E=512, window=64
#define B_  2
#define L_  2048
#define E_  512
#define WIN 64

// ---------------- scratch (device globals; no cudaMalloc allowed) ----------
// split-precision bf16 pairs: value ~= hi + lo (residual ~2^-16 relative)
__device__ __nv_bfloat16 g_xhi[B_ * L_ * E_], g_xlo[B_ * L_ * E_];
__device__ __nv_bfloat16 g_whi[3 * E_ * E_], g_wlo[3 * E_ * E_];
__device__ __nv_bfloat16 g_qhi[B_ * L_ * E_], g_qlo[B_ * L_ * E_];
__device__ __nv_bfloat16 g_khi[B_ * L_ * E_], g_klo[B_ * L_ * E_];
__device__ __nv_bfloat16 g_vhi[B_ * L_ * E_], g_vlo[B_ * L_ * E_];

// ============================================================================
// Warp-level tensor-core + async-copy primitives (baseline PTX, compute_103)
// ============================================================================
static __device__ __forceinline__ uint32_t smem_u32(const void* p) {
    uint32_t a;
    asm("{ .reg .u64 t; cvta.to.shared.u64 t, %1; cvt.u32.u64 %0, t; }"
        : "=r"(a) : "l"(p));
    return a;
}

static __device__ __forceinline__ void ldsm_x4(uint32_t (&r)[4], uint32_t addr)
{
    asm volatile("ldmatrix.sync.aligned.m8n8.x4.shared.b16 {%0,%1,%2,%3}, [%4];"
        : "=r"(r[0]), "=r"(r[1]), "=r"(r[2]), "=r"(r[3]) : "r"(addr));
}

static __device__ __forceinline__ void ldsm_x4_t(uint32_t (&r)[4], uint32_t addr)
{
    asm volatile("ldmatrix.sync.aligned.m8n8.x4.trans.shared.b16 {%0,%1,%2,%3}, [%4];"
        : "=r"(r[0]), "=r"(r[1]), "=r"(r[2]), "=r"(r[3]) : "r"(addr));
}

static __device__ __forceinline__ void mma16816(
    float (&c)[4], const uint32_t (&a)[4], uint32_t b0, uint32_t b1)
{
    asm volatile(
        "mma.sync.aligned.m16n8k16.row.col.f32.bf16.bf16.f32 "
        "{%0,%1,%2,%3}, {%4,%5,%6,%7}, {%8,%9}, {%0,%1,%2,%3};"
        : "+f"(c[0]), "+f"(c[1]), "+f"(c[2]), "+f"(c[3])
        : "r"(a[0]), "r"(a[1]), "r"(a[2]), "r"(a[3]), "r"(b0), "r"(b1));
}

// 16B global->shared async copy
static __device__ __forceinline__ void cp16(uint32_t dst, const void* src)
{
    asm volatile("cp.async.cg.shared.global [%0], [%1], 16;"
        :: "r"(dst), "l"(src));
}
// predicated: pred==false -> zero-fill 16B (src must still be a valid address)
static __device__ __forceinline__ void cp16z(uint32_t dst, const void* src, bool pred)
{
    int sz = pred ? 16 : 0;
    asm volatile("cp.async.cg.shared.global [%0], [%1], 16, %2;"
        :: "r"(dst), "l"(src), "r"(sz));
}
#define CP_COMMIT() asm volatile("cp.async.commit_group;" ::: "memory")
#define CP_WAIT(n)  asm volatile("cp.async.wait_group %0;" :: "n"(n) : "memory")

// fp32 -> (bf16 hi, bf16 lo) split, 4-wide
static __device__ __forceinline__ void cvt_split(float4 f, uint2& hi, uint2& lo)
{
    float v[4] = {f.x, f.y, f.z, f.w};
    unsigned short h[4], l[4];
#pragma unroll
    for (int i = 0; i < 4; i++) {
        __nv_bfloat16 hb = __float2bfloat16(v[i]);
        float r = v[i] - __bfloat162float(hb);
        __nv_bfloat16 lb = __float2bfloat16(r);
        h[i] = __bfloat16_as_ushort(hb);
        l[i] = __bfloat16_as_ushort(lb);
    }
    hi.x = (uint32_t)h[0] | ((uint32_t)h[1] << 16);
    hi.y = (uint32_t)h[2] | ((uint32_t)h[3] << 16);
    lo.x = (uint32_t)l[0] | ((uint32_t)l[1] << 16);
    lo.y = (uint32_t)l[2] | ((uint32_t)l[3] << 16);
}

static __device__ __forceinline__ void split2_store(
    __nv_bfloat16* hi, __nv_bfloat16* lo, size_t off, float a, float b)
{
    __nv_bfloat16 ha = __float2bfloat16(a), hb = __float2bfloat16(b);
    __nv_bfloat16 la = __float2bfloat16(a - __bfloat162float(ha));
    __nv_bfloat16 lb = __float2bfloat16(b - __bfloat162float(hb));
    *(__nv_bfloat162*)(hi + off) = __halves2bfloat162(ha, hb);
    *(__nv_bfloat162*)(lo + off) = __halves2bfloat162(la, lb);
}

// ============================================================================
// Pre-pass: split fp32 X / Wq / Wk / Wv into bf16 hi/lo global arrays.
// ============================================================================
__global__ __launch_bounds__(256) void split_all(
    const float* __restrict__ X,  const float* __restrict__ Wq,
    const float* __restrict__ Wk, const float* __restrict__ Wv)
{
    const float* src; __nv_bfloat16 *hi, *lo; int n4;
    switch (blockIdx.y) {
        case 0:  src = X;  hi = g_xhi;           lo = g_xlo;           n4 = (B_*L_*E_)/4; break;
        case 1:  src = Wq; hi = g_whi;           lo = g_wlo;           n4 = (E_*E_)/4;    break;
        case 2:  src = Wk; hi = g_whi + E_*E_;   lo = g_wlo + E_*E_;   n4 = (E_*E_)/4;    break;
        default: src = Wv; hi = g_whi + 2*E_*E_; lo = g_wlo + 2*E_*E_; n4 = (E_*E_)/4;    break;
    }
    for (int i = blockIdx.x * blockDim.x + threadIdx.x; i < n4;
         i += gridDim.x * blockDim.x) {
        float4 v = ((const float4*)src)[i];
        uint2 h, l; cvt_split(v, h, l);
        ((uint2*)hi)[i] = h;
        ((uint2*)lo)[i] = l;
    }
}

// ============================================================================
// QKV GEMM on tensor cores, cp.async double-buffered pipeline.
// C = X @ W^T + bias; M=4096, N=512, K=512. CTA 128x128, K chunks of 64.
// Per stage: A_hi/A_lo/B_hi/B_lo bf16 tiles (128 x 64, row stride 72 bf16).
// 8 warps = 2(M) x 4(N); splits Ahi*Bhi + Ahi*Blo + Alo*Bhi.
// ============================================================================
#define STRH  72                      // smem row stride (bf16 units)
#define TILEB (128 * STRH * 2)        // 18432 bytes per tile
#define QSTG  (4 * TILEB)             // 73728 bytes per stage
#define QT_SMEM (2 * QSTG)            // 147456 bytes

__global__ __launch_bounds__(256) void qkv_tc(
    const float* __restrict__ b0p, const float* __restrict__ b1p,
    const float* __restrict__ b2p)
{
    extern __shared__ __align__(16) char smem[];
    const uint32_t sb = smem_u32(smem);

    const int z = blockIdx.z;
    const __nv_bfloat16* Whi = g_whi + (size_t)z * E_ * E_;
    const __nv_bfloat16* Wlo = g_wlo + (size_t)z * E_ * E_;
    __nv_bfloat16 *Chi, *Clo; const float* bias;
    if (z == 0)      { Chi = g_qhi; Clo = g_qlo; bias = b0p; }
    else if (z == 1) { Chi = g_khi; Clo = g_klo; bias = b1p; }
    else             { Chi = g_vhi; Clo = g_vlo; bias = b2p; }

    const int m0  = blockIdx.x * 128;
    const int n0  = blockIdx.y * 128;
    const int t   = threadIdx.x;
    const int wid = t >> 5;
    const int lid = t & 31;
    const int wm  = wid & 1;
    const int wn  = wid >> 1;

    float acc[4][4][4];
#pragma unroll
    for (int mi = 0; mi < 4; mi++)
#pragma unroll
        for (int ni = 0; ni < 4; ni++)
#pragma unroll
            for (int r = 0; r < 4; r++) acc[mi][ni][r] = 0.f;

    const int g = lid >> 3, r8 = lid & 7;
    const uint32_t aLaneOff = (uint32_t)((((g & 1) * 8 + r8) * STRH + (g >> 1) * 8) * 2);
    const uint32_t bLaneOff = (uint32_t)((((g >> 1) * 8 + r8) * STRH + (g & 1) * 8) * 2);

    // async load of one K-chunk (4 tiles) into stage buf
    auto load_chunk = [&](int ck, int buf) {
        const int k0 = ck * 64;
        const uint32_t bpa = sb + (uint32_t)buf * QSTG;
#pragma unroll
        for (int it = 0; it < 4; it++) {
            int idx = t + it * 256;
            int row = idx >> 3, c8 = idx & 7;
            uint32_t off = (uint32_t)(row * (STRH * 2) + c8 * 16);
            size_t ax = (size_t)(m0 + row) * E_ + k0 + c8 * 8;
            size_t bx = (size_t)(n0 + row) * E_ + k0 + c8 * 8;
            cp16(bpa + off,             g_xhi + ax);
            cp16(bpa + TILEB + off,     g_xlo + ax);
            cp16(bpa + 2 * TILEB + off, Whi + bx);
            cp16(bpa + 3 * TILEB + off, Wlo + bx);
        }
    };

    load_chunk(0, 0);
    CP_COMMIT();

    for (int ck = 0; ck < 8; ck++) {
        const int buf = ck & 1;
        if (ck < 7) {
            load_chunk(ck + 1, buf ^ 1);
            CP_COMMIT();
            CP_WAIT(1);
        } else {
            CP_WAIT(0);
        }
        __syncthreads();

        const uint32_t bp = sb + (uint32_t)buf * QSTG;
#pragma unroll
        for (int kk = 0; kk < 4; kk++) {
            const uint32_t kOff = (uint32_t)(kk * 32);
            uint32_t aH[4][4], aL[4][4], bH[2][4], bL[2][4];
#pragma unroll
            for (int mi = 0; mi < 4; mi++) {
                uint32_t rowOff = (uint32_t)((wm * 64 + mi * 16) * (STRH * 2));
                ldsm_x4(aH[mi], bp + rowOff + kOff + aLaneOff);
                ldsm_x4(aL[mi], bp + TILEB + rowOff + kOff + aLaneOff);
            }
#pragma unroll
            for (int nj = 0; nj < 2; nj++) {
                uint32_t rowOff = (uint32_t)((wn * 32 + nj * 16) * (STRH * 2));
                ldsm_x4(bH[nj], bp + 2 * TILEB + rowOff + kOff + bLaneOff);
                ldsm_x4(bL[nj], bp + 3 * TILEB + rowOff + kOff + bLaneOff);
            }
#pragma unroll
            for (int mi = 0; mi < 4; mi++)
#pragma unroll
                for (int ni = 0; ni < 4; ni++) {
                    uint32_t h0 = bH[ni >> 1][(ni & 1) * 2];
                    uint32_t h1 = bH[ni >> 1][(ni & 1) * 2 + 1];
                    uint32_t l0 = bL[ni >> 1][(ni & 1) * 2];
                    uint32_t l1 = bL[ni >> 1][(ni & 1) * 2 + 1];
                    mma16816(acc[mi][ni], aH[mi], h0, h1);   // hi*hi
                    mma16816(acc[mi][ni], aH[mi], l0, l1);   // hi*lo
                    mma16816(acc[mi][ni], aL[mi], h0, h1);   // lo*hi
                }
        }
        __syncthreads();   // before next iteration overwrites buf^1
    }

    // epilogue: bias add (fp32), split-store to hi/lo bf16 outputs
    const int qg = lid >> 2;
    const int qi = lid & 3;
#pragma unroll
    for (int ni = 0; ni < 4; ni++) {
        int col = n0 + wn * 32 + ni * 8 + qi * 2;
        float2 bb = *(const float2*)&bias[col];
#pragma unroll
        for (int mi = 0; mi < 4; mi++) {
            int row = m0 + wm * 64 + mi * 16 + qg;
            split2_store(Chi, Clo, (size_t)row * E_ + col,
                         acc[mi][ni][0] + bb.x, acc[mi][ni][1] + bb.y);
            split2_store(Chi, Clo, (size_t)(row + 8) * E_ + col,
                         acc[mi][ni][2] + bb.x, acc[mi][ni][3] + bb.y);
        }
    }
}

// ============================================================================
// Banded local attention, tensor cores + cp.async pipeline.
// Block = 32 queries. Key rows [q0-64, q0+95] -> 160, padded to 192.
// ============================================================================
#define TQ   32
#define NR   160
#define NRP  192
#define ACH  64
#define PSTR 200          // P smem stride (bf16)
#define SSTA 161          // scores fp32 stride

// per-stage layout (bytes)
#define SO_QHI 0
#define SO_QLO (SO_QHI + TQ * STRH * 2)        // 4608
#define SO_KHI (SO_QLO + TQ * STRH * 2)        // 9216
#define SO_KLO (SO_KHI + NRP * STRH * 2)       // 36864
#define ASTG   (SO_KLO + NRP * STRH * 2)       // 64512 per stage
#define O_SC   (2 * ASTG)                      // 129024
#define O_PHI  (O_SC + TQ * SSTA * 4)          // 149632
#define O_PLO  (O_PHI + TQ * PSTR * 2)         // 162432
#define A_SMEM (O_PLO + TQ * PSTR * 2)         // 175232 bytes

__global__ __launch_bounds__(256) void attn_tc(float* __restrict__ out)
{
    extern __shared__ __align__(16) char smem[];
    const uint32_t sb = smem_u32(smem);
    float* scS = (float*)(smem + O_SC);

    const int q0  = blockIdx.x * TQ;
    const int b   = blockIdx.y;
    const int t   = threadIdx.x;
    const int wid = t >> 5;
    const int lid = t & 31;
    const int g   = lid >> 3, r8 = lid & 7;
    const size_t base = (size_t)b * (L_ * E_);

    const uint32_t aOff  = (uint32_t)((((g & 1) * 8 + r8) * STRH + (g >> 1) * 8) * 2);
    const uint32_t bOff  = (uint32_t)((((g >> 1) * 8 + r8) * STRH + (g & 1) * 8) * 2);
    const uint32_t aPOff = (uint32_t)((((g & 1) * 8 + r8) * PSTR + (g >> 1) * 8) * 2);

    // ---- async chunk loaders ------------------------------------------------
    auto load_qk = [&](int ec, int stg) {
        const uint32_t sa = sb + (uint32_t)stg * ASTG;
        {   // Q tile 32x64
            int row = t >> 3, c8 = t & 7;
            uint32_t off = (uint32_t)(row * (STRH * 2) + c8 * 16);
            size_t gi = base + (size_t)(q0 + row) * E_ + ec + c8 * 8;
            cp16(sa + SO_QHI + off, g_qhi + gi);
            cp16(sa + SO_QLO + off, g_qlo + gi);
        }
#pragma unroll
        for (int it = 0; it < 5; it++) {    // K rows 0..159
            int idx = t + it * 256;
            int row = idx >> 3, c8 = idx & 7;
            int kg  = q0 - WIN + row;
            bool ok = (kg >= 0) && (kg < L_);
            size_t gi = base + (size_t)(ok ? kg : 0) * E_ + ec + c8 * 8;
            uint32_t off = (uint32_t)(row * (STRH * 2) + c8 * 16);
            cp16z(sa + SO_KHI + off, g_khi + gi, ok);
            cp16z(sa + SO_KLO + off, g_klo + gi, ok);
        }
    };
    auto load_v = [&](int ec, int stg) {
        const uint32_t sa = sb + (uint32_t)stg * ASTG;
#pragma unroll
        for (int it = 0; it < 5; it++) {    // V rows 0..159 (pad zeroed once)
            int idx = t + it * 256;
            int row = idx >> 3, c8 = idx & 7;
            int kg  = q0 - WIN + row;
            bool ok = (kg >= 0) && (kg < L_);
            size_t gi = base + (size_t)(ok ? kg : 0) * E_ + ec + c8 * 8;
            uint32_t off = (uint32_t)(row * (STRH * 2) + c8 * 16);
            cp16z(sa + SO_KHI + off, g_vhi + gi, ok);
            cp16z(sa + SO_KLO + off, g_vlo + gi, ok);
        }
    };

    // ---------------- Phase 1: S = Q K^T (pipelined over 8 e-chunks) -------
    float acc[2][3][4];
#pragma unroll
    for (int mi = 0; mi < 2; mi++)
#pragma unroll
        for (int nj = 0; nj < 3; nj++)
#pragma unroll
            for (int r = 0; r < 4; r++) acc[mi][nj][r] = 0.f;

    load_qk(0, 0);
    CP_COMMIT();

    for (int ci = 0; ci < 8; ci++) {
        const int stg = ci & 1;
        if (ci < 7) {
            load_qk((ci + 1) * ACH, stg ^ 1);
            CP_COMMIT();
            CP_WAIT(1);
        } else {
            CP_WAIT(0);
        }
        __syncthreads();

        const uint32_t sa = sb + (uint32_t)stg * ASTG;
#pragma unroll
        for (int kk = 0; kk < 4; kk++) {
            const uint32_t kOff = (uint32_t)(kk * 32);
            uint32_t aH[2][4], aL[2][4];
#pragma unroll
            for (int mi = 0; mi < 2; mi++) {
                uint32_t rowOff = (uint32_t)(mi * 16 * (STRH * 2));
                ldsm_x4(aH[mi], sa + SO_QHI + rowOff + kOff + aOff);
                ldsm_x4(aL[mi], sa + SO_QLO + rowOff + kOff + aOff);
            }
            const uint32_t nb0 = (uint32_t)(wid * 24 * (STRH * 2));
            const uint32_t nb1 = (uint32_t)((wid * 24 + 16) * (STRH * 2));
            uint32_t bH0[4], bH1[4], bL0[4], bL1[4];
            ldsm_x4(bH0, sa + SO_KHI + nb0 + kOff + bOff);
            ldsm_x4(bH1, sa + SO_KHI + nb1 + kOff + bOff);
            ldsm_x4(bL0, sa + SO_KLO + nb0 + kOff + bOff);
            ldsm_x4(bL1, sa + SO_KLO + nb1 + kOff + bOff);
#pragma unroll
            for (int mi = 0; mi < 2; mi++)
#pragma unroll
                for (int nj = 0; nj < 3; nj++) {
                    uint32_t h0 = (nj < 2) ? bH0[nj * 2]     : bH1[0];
                    uint32_t h1 = (nj < 2) ? bH0[nj * 2 + 1] : bH1[1];
                    uint32_t l0 = (nj < 2) ? bL0[nj * 2]     : bL1[0];
                    uint32_t l1 = (nj < 2) ? bL0[nj * 2 + 1] : bL1[1];
                    mma16816(acc[mi][nj], aH[mi], h0, h1);
                    mma16816(acc[mi][nj], aH[mi], l0, l1);
                    mma16816(acc[mi][nj], aL[mi], h0, h1);
                }
        }
        __syncthreads();
    }

    // write scores (n < 160 only) to fp32 smem
    {
        const int rA = lid >> 2, cA = (lid & 3) * 2;
#pragma unroll
        for (int mi = 0; mi < 2; mi++)
#pragma unroll
            for (int nj = 0; nj < 3; nj++) {
                int n = wid * 24 + nj * 8 + cA;
                if (n < NR) {
                    int r0 = mi * 16 + rA;
                    scS[r0 * SSTA + n]           = acc[mi][nj][0];
                    scS[r0 * SSTA + n + 1]       = acc[mi][nj][1];
                    scS[(r0 + 8) * SSTA + n]     = acc[mi][nj][2];
                    scS[(r0 + 8) * SSTA + n + 1] = acc[mi][nj][3];
                }
            }
    }

    // prefetch V chunk 0 into stage 0 while softmax runs
    load_v(0, 0);
    CP_COMMIT();

    // zero the pad rows (160..191) of BOTH stages once: 4 uint4 per thread
    {
        uint4 zz = make_uint4(0, 0, 0, 0);
#pragma unroll
        for (int s = 0; s < 2; s++) {
            int idx = t;                    // 256 threads cover 32 rows x 8 c8
            int row = NR + (idx >> 3), c8 = idx & 7;
            uint32_t off = (uint32_t)(row * (STRH * 2) + c8 * 16);
            char* sa = smem + s * ASTG;
            *(uint4*)(sa + SO_KHI + off) = zz;
            *(uint4*)(sa + SO_KLO + off) = zz;
        }
    }
    __syncthreads();

    // ---------------- Softmax (fp32), emit P as split bf16 ------------------
    {
        const float inv_sqrt_e = 0.04419417382415922f;  // 1/sqrt(512)
        const int qi  = t >> 3;
        const int sub = t & 7;
        float vals[20];
        float m = -INFINITY;
#pragma unroll
        for (int u = 0; u < 20; u++) {
            int r  = sub * 20 + u;
            int wj = r - qi;
            int kg = q0 + r - WIN;
            bool valid = (wj >= 0) && (wj <= 2 * WIN) && (kg >= 0) && (kg < L_);
            float s = valid ? scS[qi * SSTA + r] * inv_sqrt_e : -INFINITY;
            vals[u] = s;
            m = fmaxf(m, s);
        }
#pragma unroll
        for (int o = 1; o < 8; o <<= 1)
            m = fmaxf(m, __shfl_xor_sync(0xffffffffu, m, o, 8));
        float ssum = 0.f;
#pragma unroll
        for (int u = 0; u < 20; u++) {
            float e = (vals[u] == -INFINITY) ? 0.f : __expf(vals[u] - m);
            vals[u] = e;
            ssum += e;
        }
#pragma unroll
        for (int o = 1; o < 8; o <<= 1)
            ssum += __shfl_xor_sync(0xffffffffu, ssum, o, 8);
        float inv = 1.f / ssum;

        __nv_bfloat16* phi = (__nv_bfloat16*)(smem + O_PHI);
        __nv_bfloat16* plo = (__nv_bfloat16*)(smem + O_PLO);
#pragma unroll
        for (int u = 0; u < 20; u++) {
            float p = vals[u] * inv;
            __nv_bfloat16 h = __float2bfloat16(p);
            __nv_bfloat16 l = __float2bfloat16(p - __bfloat162float(h));
            phi[qi * PSTR + sub * 20 + u] = h;
            plo[qi * PSTR + sub * 20 + u] = l;
        }
        // zero pad columns 160..191 (k-dim padding for phase 2)
        __nv_bfloat16 z = __float2bfloat16(0.0f);
#pragma unroll
        for (int u = 0; u < 4; u++) {
            int r = NR + sub * 4 + u;
            phi[qi * PSTR + r] = z;
            plo[qi * PSTR + r] = z;
        }
    }
    __syncthreads();

    // ---------------- Phase 2: out = P @ V (pipelined over 8 e-chunks) -----
    float* gout = out + base;
    for (int ci = 0; ci < 8; ci++) {
        const int stg = ci & 1;
        if (ci < 7) {
            load_v((ci + 1) * ACH, stg ^ 1);
            CP_COMMIT();
            CP_WAIT(1);
        } else {
            CP_WAIT(0);
        }
        __syncthreads();

        const uint32_t sa = sb + (uint32_t)stg * ASTG;
        float o[2][4];
#pragma unroll
        for (int mi = 0; mi < 2; mi++)
#pragma unroll
            for (int r = 0; r < 4; r++) o[mi][r] = 0.f;

#pragma unroll
        for (int ks = 0; ks < 6; ks++) {   // k32 per iteration (192 total)
            uint32_t vrow = (uint32_t)((ks * 32 + lid) * (STRH * 2) + wid * 16);
            uint32_t vH[4], vL[4];
            ldsm_x4_t(vH, sa + SO_KHI + vrow);
            ldsm_x4_t(vL, sa + SO_KLO + vrow);
#pragma unroll
            for (int half = 0; half < 2; half++) {
                uint32_t kOff = (uint32_t)((ks * 32 + half * 16) * 2);
                uint32_t aH[2][4], aL[2][4];
#pragma unroll
                for (int mi = 0; mi < 2; mi++) {
                    uint32_t rowOff = (uint32_t)(mi * 16 * (PSTR * 2));
                    ldsm_x4(aH[mi], sb + O_PHI + rowOff + kOff + aPOff);
                    ldsm_x4(aL[mi], sb + O_PLO + rowOff + kOff + aPOff);
                }
                uint32_t h0 = vH[half * 2], h1 = vH[half * 2 + 1];
                uint32_t l0 = vL[half * 2], l1 = vL[half * 2 + 1];
#pragma unroll
                for (int mi = 0; mi < 2; mi++) {
                    mma16816(o[mi], aH[mi], h0, h1);   // Phi*Vhi
                    mma16816(o[mi], aH[mi], l0, l1);   // Phi*Vlo
                    mma16816(o[mi], aL[mi], h0, h1);   // Plo*Vhi
                }
            }
        }

        {   // store fp32 output
            int col = ci * ACH + wid * 8 + (lid & 3) * 2;
#pragma unroll
            for (int mi = 0; mi < 2; mi++) {
                int r = q0 + mi * 16 + (lid >> 2);
                *(float2*)&gout[(size_t)r * E_ + col] =
                    make_float2(o[mi][0], o[mi][1]);
                *(float2*)&gout[(size_t)(r + 8) * E_ + col] =
                    make_float2(o[mi][2], o[mi][3]);
            }
        }
        __syncthreads();
    }
}

// ============================================================================
extern "C" void kernel_launch(void* const* d_in, const int* in_sizes, int n_in,
                              void* d_out, int out_size)
{
    const float* x  = (const float*)d_in[0];
    const float* Wq = (const float*)d_in[1];
    const float* bq = (const float*)d_in[2];
    const float* Wk = (const float*)d_in[3];
    const float* bk = (const float*)d_in[4];
    const float* Wv = (const float*)d_in[5];
    const float* bv = (const float*)d_in[6];
    float* out = (float*)d_out;

    // 1) split X / W into bf16 hi/lo
    split_all<<<dim3(512, 4), 256>>>(x, Wq, Wk, Wv);

    // 2) QKV projections on tensor cores -> split bf16 q/k/v
    cudaFuncSetAttribute(qkv_tc, cudaFuncAttributeMaxDynamicSharedMemorySize,
                         QT_SMEM);
    dim3 ggrid((B_ * L_) / 128, E_ / 128, 3);
    qkv_tc<<<ggrid, 256, QT_SMEM>>>(bq, bk, bv);

    // 3) banded attention on tensor cores
    cudaFuncSetAttribute(attn_tc, cudaFuncAttributeMaxDynamicSharedMemorySize,
                         A_SMEM);
    dim3 agrid(L_ / TQ, B_);
    attn_tc<<<agrid, 256, A_SMEM>>>(out);
}

// round 16
// speedup vs baseline: 1.0025x; 1.0025x over previous
#include <cuda_runtime.h>
#include <cuda_bf16.h>
#include <math.h>
#include <stdint.h>

// Problem shapes (fixed by setup_inputs): B=2, L=2048, E=512, window=64
#define B_  2
#define L_  2048
#define E_  512
#define WIN 64

// ---------------- scratch (device globals; no cudaMalloc allowed) ----------
// split-precision bf16 pairs: value ~= hi + lo (residual ~2^-16 relative)
__device__ __nv_bfloat16 g_xhi[B_ * L_ * E_], g_xlo[B_ * L_ * E_];
__device__ __nv_bfloat16 g_whi[3 * E_ * E_], g_wlo[3 * E_ * E_];
__device__ __nv_bfloat16 g_qhi[B_ * L_ * E_], g_qlo[B_ * L_ * E_];
__device__ __nv_bfloat16 g_khi[B_ * L_ * E_], g_klo[B_ * L_ * E_];
__device__ __nv_bfloat16 g_vhi[B_ * L_ * E_], g_vlo[B_ * L_ * E_];

// ============================================================================
// Warp-level tensor-core + async-copy primitives (baseline PTX, compute_103)
// ============================================================================
static __device__ __forceinline__ uint32_t smem_u32(const void* p) {
    uint32_t a;
    asm("{ .reg .u64 t; cvta.to.shared.u64 t, %1; cvt.u32.u64 %0, t; }"
        : "=r"(a) : "l"(p));
    return a;
}

static __device__ __forceinline__ void ldsm_x4(uint32_t (&r)[4], uint32_t addr)
{
    asm volatile("ldmatrix.sync.aligned.m8n8.x4.shared.b16 {%0,%1,%2,%3}, [%4];"
        : "=r"(r[0]), "=r"(r[1]), "=r"(r[2]), "=r"(r[3]) : "r"(addr));
}

static __device__ __forceinline__ void ldsm_x4_t(uint32_t (&r)[4], uint32_t addr)
{
    asm volatile("ldmatrix.sync.aligned.m8n8.x4.trans.shared.b16 {%0,%1,%2,%3}, [%4];"
        : "=r"(r[0]), "=r"(r[1]), "=r"(r[2]), "=r"(r[3]) : "r"(addr));
}

static __device__ __forceinline__ void mma16816(
    float (&c)[4], const uint32_t (&a)[4], uint32_t b0, uint32_t b1)
{
    asm volatile(
        "mma.sync.aligned.m16n8k16.row.col.f32.bf16.bf16.f32 "
        "{%0,%1,%2,%3}, {%4,%5,%6,%7}, {%8,%9}, {%0,%1,%2,%3};"
        : "+f"(c[0]), "+f"(c[1]), "+f"(c[2]), "+f"(c[3])
        : "r"(a[0]), "r"(a[1]), "r"(a[2]), "r"(a[3]), "r"(b0), "r"(b1));
}

// 16B global->shared async copy
static __device__ __forceinline__ void cp16(uint32_t dst, const void* src)
{
    asm volatile("cp.async.cg.shared.global [%0], [%1], 16;"
        :: "r"(dst), "l"(src));
}
// predicated: pred==false -> zero-fill 16B (src must still be a valid address)
static __device__ __forceinline__ void cp16z(uint32_t dst, const void* src, bool pred)
{
    int sz = pred ? 16 : 0;
    asm volatile("cp.async.cg.shared.global [%0], [%1], 16, %2;"
        :: "r"(dst), "l"(src), "r"(sz));
}
#define CP_COMMIT() asm volatile("cp.async.commit_group;" ::: "memory")
#define CP_WAIT(n)  asm volatile("cp.async.wait_group %0;" :: "n"(n) : "memory")

// fp32 -> (bf16 hi, bf16 lo) split, 4-wide
static __device__ __forceinline__ void cvt_split(float4 f, uint2& hi, uint2& lo)
{
    float v[4] = {f.x, f.y, f.z, f.w};
    unsigned short h[4], l[4];
#pragma unroll
    for (int i = 0; i < 4; i++) {
        __nv_bfloat16 hb = __float2bfloat16(v[i]);
        float r = v[i] - __bfloat162float(hb);
        __nv_bfloat16 lb = __float2bfloat16(r);
        h[i] = __bfloat16_as_ushort(hb);
        l[i] = __bfloat16_as_ushort(lb);
    }
    hi.x = (uint32_t)h[0] | ((uint32_t)h[1] << 16);
    hi.y = (uint32_t)h[2] | ((uint32_t)h[3] << 16);
    lo.x = (uint32_t)l[0] | ((uint32_t)l[1] << 16);
    lo.y = (uint32_t)l[2] | ((uint32_t)l[3] << 16);
}

static __device__ __forceinline__ void split2_store(
    __nv_bfloat16* hi, __nv_bfloat16* lo, size_t off, float a, float b)
{
    __nv_bfloat16 ha = __float2bfloat16(a), hb = __float2bfloat16(b);
    __nv_bfloat16 la = __float2bfloat16(a - __bfloat162float(ha));
    __nv_bfloat16 lb = __float2bfloat16(b - __bfloat162float(hb));
    *(__nv_bfloat162*)(hi + off) = __halves2bfloat162(ha, hb);
    *(__nv_bfloat162*)(lo + off) = __halves2bfloat162(la, lb);
}

// ============================================================================
// Pre-pass: split fp32 X / Wq / Wk / Wv into bf16 hi/lo global arrays.
// ============================================================================
__global__ __launch_bounds__(256) void split_all(
    const float* __restrict__ X,  const float* __restrict__ Wq,
    const float* __restrict__ Wk, const float* __restrict__ Wv)
{
    const float* src; __nv_bfloat16 *hi, *lo; int n4;
    switch (blockIdx.y) {
        case 0:  src = X;  hi = g_xhi;           lo = g_xlo;           n4 = (B_*L_*E_)/4; break;
        case 1:  src = Wq; hi = g_whi;           lo = g_wlo;           n4 = (E_*E_)/4;    break;
        case 2:  src = Wk; hi = g_whi + E_*E_;   lo = g_wlo + E_*E_;   n4 = (E_*E_)/4;    break;
        default: src = Wv; hi = g_whi + 2*E_*E_; lo = g_wlo + 2*E_*E_; n4 = (E_*E_)/4;    break;
    }
    for (int i = blockIdx.x * blockDim.x + threadIdx.x; i < n4;
         i += gridDim.x * blockDim.x) {
        float4 v = ((const float4*)src)[i];
        uint2 h, l; cvt_split(v, h, l);
        ((uint2*)hi)[i] = h;
        ((uint2*)lo)[i] = l;
    }
}

// ============================================================================
// QKV GEMM on tensor cores, cp.async double-buffered pipeline.
// C = X @ W^T + bias; M=4096, N=512, K=512. CTA 128x128, K chunks of 64.
// Per stage: A_hi/A_lo/B_hi/B_lo bf16 tiles (128 x 64, row stride 72 bf16).
// 8 warps = 2(M) x 4(N); splits Ahi*Bhi + Ahi*Blo + Alo*Bhi.
// ============================================================================
#define STRH  72                      // smem row stride (bf16 units)
#define TILEB (128 * STRH * 2)        // 18432 bytes per tile
#define QSTG  (4 * TILEB)             // 73728 bytes per stage
#define QT_SMEM (2 * QSTG)            // 147456 bytes

__global__ __launch_bounds__(256) void qkv_tc(
    const float* __restrict__ b0p, const float* __restrict__ b1p,
    const float* __restrict__ b2p)
{
    extern __shared__ __align__(16) char smem[];
    const uint32_t sb = smem_u32(smem);

    const int z = blockIdx.z;
    const __nv_bfloat16* Whi = g_whi + (size_t)z * E_ * E_;
    const __nv_bfloat16* Wlo = g_wlo + (size_t)z * E_ * E_;
    __nv_bfloat16 *Chi, *Clo; const float* bias;
    if (z == 0)      { Chi = g_qhi; Clo = g_qlo; bias = b0p; }
    else if (z == 1) { Chi = g_khi; Clo = g_klo; bias = b1p; }
    else             { Chi = g_vhi; Clo = g_vlo; bias = b2p; }

    const int m0  = blockIdx.x * 128;
    const int n0  = blockIdx.y * 128;
    const int t   = threadIdx.x;
    const int wid = t >> 5;
    const int lid = t & 31;
    const int wm  = wid & 1;
    const int wn  = wid >> 1;

    float acc[4][4][4];
#pragma unroll
    for (int mi = 0; mi < 4; mi++)
#pragma unroll
        for (int ni = 0; ni < 4; ni++)
#pragma unroll
            for (int r = 0; r < 4; r++) acc[mi][ni][r] = 0.f;

    const int g = lid >> 3, r8 = lid & 7;
    const uint32_t aLaneOff = (uint32_t)((((g & 1) * 8 + r8) * STRH + (g >> 1) * 8) * 2);
    const uint32_t bLaneOff = (uint32_t)((((g >> 1) * 8 + r8) * STRH + (g & 1) * 8) * 2);

    // async load of one K-chunk (4 tiles) into stage buf
    auto load_chunk = [&](int ck, int buf) {
        const int k0 = ck * 64;
        const uint32_t bpa = sb + (uint32_t)buf * QSTG;
#pragma unroll
        for (int it = 0; it < 4; it++) {
            int idx = t + it * 256;
            int row = idx >> 3, c8 = idx & 7;
            uint32_t off = (uint32_t)(row * (STRH * 2) + c8 * 16);
            size_t ax = (size_t)(m0 + row) * E_ + k0 + c8 * 8;
            size_t bx = (size_t)(n0 + row) * E_ + k0 + c8 * 8;
            cp16(bpa + off,             g_xhi + ax);
            cp16(bpa + TILEB + off,     g_xlo + ax);
            cp16(bpa + 2 * TILEB + off, Whi + bx);
            cp16(bpa + 3 * TILEB + off, Wlo + bx);
        }
    };

    load_chunk(0, 0);
    CP_COMMIT();

    for (int ck = 0; ck < 8; ck++) {
        const int buf = ck & 1;
        if (ck < 7) {
            load_chunk(ck + 1, buf ^ 1);
            CP_COMMIT();
            CP_WAIT(1);
        } else {
            CP_WAIT(0);
        }
        __syncthreads();

        const uint32_t bp = sb + (uint32_t)buf * QSTG;
#pragma unroll
        for (int kk = 0; kk < 4; kk++) {
            const uint32_t kOff = (uint32_t)(kk * 32);
            uint32_t aH[4][4], aL[4][4], bH[2][4], bL[2][4];
#pragma unroll
            for (int mi = 0; mi < 4; mi++) {
                uint32_t rowOff = (uint32_t)((wm * 64 + mi * 16) * (STRH * 2));
                ldsm_x4(aH[mi], bp + rowOff + kOff + aLaneOff);
                ldsm_x4(aL[mi], bp + TILEB + rowOff + kOff + aLaneOff);
            }
#pragma unroll
            for (int nj = 0; nj < 2; nj++) {
                uint32_t rowOff = (uint32_t)((wn * 32 + nj * 16) * (STRH * 2));
                ldsm_x4(bH[nj], bp + 2 * TILEB + rowOff + kOff + bLaneOff);
                ldsm_x4(bL[nj], bp + 3 * TILEB + rowOff + kOff + bLaneOff);
            }
#pragma unroll
            for (int mi = 0; mi < 4; mi++)
#pragma unroll
                for (int ni = 0; ni < 4; ni++) {
                    uint32_t h0 = bH[ni >> 1][(ni & 1) * 2];
                    uint32_t h1 = bH[ni >> 1][(ni & 1) * 2 + 1];
                    uint32_t l0 = bL[ni >> 1][(ni & 1) * 2];
                    uint32_t l1 = bL[ni >> 1][(ni & 1) * 2 + 1];
                    mma16816(acc[mi][ni], aH[mi], h0, h1);   // hi*hi
                    mma16816(acc[mi][ni], aH[mi], l0, l1);   // hi*lo
                    mma16816(acc[mi][ni], aL[mi], h0, h1);   // lo*hi
                }
        }
        __syncthreads();   // before next iteration overwrites buf^1
    }

    // epilogue: bias add (fp32), split-store to hi/lo bf16 outputs
    const int qg = lid >> 2;
    const int qi = lid & 3;
#pragma unroll
    for (int ni = 0; ni < 4; ni++) {
        int col = n0 + wn * 32 + ni * 8 + qi * 2;
        float2 bb = *(const float2*)&bias[col];
#pragma unroll
        for (int mi = 0; mi < 4; mi++) {
            int row = m0 + wm * 64 + mi * 16 + qg;
            split2_store(Chi, Clo, (size_t)row * E_ + col,
                         acc[mi][ni][0] + bb.x, acc[mi][ni][1] + bb.y);
            split2_store(Chi, Clo, (size_t)(row + 8) * E_ + col,
                         acc[mi][ni][2] + bb.x, acc[mi][ni][3] + bb.y);
        }
    }
}

// ============================================================================
// Banded local attention, tensor cores + cp.async pipeline.
// Block = 32 queries. Key rows [q0-64, q0+95] -> 160, padded to 192.
// ============================================================================
#define TQ   32
#define NR   160
#define NRP  192
#define ACH  64
#define PSTR 200          // P smem stride (bf16)
#define SSTA 161          // scores fp32 stride

// per-stage layout (bytes)
#define SO_QHI 0
#define SO_QLO (SO_QHI + TQ * STRH * 2)        // 4608
#define SO_KHI (SO_QLO + TQ * STRH * 2)        // 9216
#define SO_KLO (SO_KHI + NRP * STRH * 2)       // 36864
#define ASTG   (SO_KLO + NRP * STRH * 2)       // 64512 per stage
#define O_SC   (2 * ASTG)                      // 129024
#define O_PHI  (O_SC + TQ * SSTA * 4)          // 149632
#define O_PLO  (O_PHI + TQ * PSTR * 2)         // 162432
#define A_SMEM (O_PLO + TQ * PSTR * 2)         // 175232 bytes

__global__ __launch_bounds__(256) void attn_tc(float* __restrict__ out)
{
    extern __shared__ __align__(16) char smem[];
    const uint32_t sb = smem_u32(smem);
    float* scS = (float*)(smem + O_SC);

    const int q0  = blockIdx.x * TQ;
    const int b   = blockIdx.y;
    const int t   = threadIdx.x;
    const int wid = t >> 5;
    const int lid = t & 31;
    const int g   = lid >> 3, r8 = lid & 7;
    const size_t base = (size_t)b * (L_ * E_);

    const uint32_t aOff  = (uint32_t)((((g & 1) * 8 + r8) * STRH + (g >> 1) * 8) * 2);
    const uint32_t bOff  = (uint32_t)((((g >> 1) * 8 + r8) * STRH + (g & 1) * 8) * 2);
    const uint32_t aPOff = (uint32_t)((((g & 1) * 8 + r8) * PSTR + (g >> 1) * 8) * 2);

    // ---- async chunk loaders ------------------------------------------------
    auto load_qk = [&](int ec, int stg) {
        const uint32_t sa = sb + (uint32_t)stg * ASTG;
        {   // Q tile 32x64
            int row = t >> 3, c8 = t & 7;
            uint32_t off = (uint32_t)(row * (STRH * 2) + c8 * 16);
            size_t gi = base + (size_t)(q0 + row) * E_ + ec + c8 * 8;
            cp16(sa + SO_QHI + off, g_qhi + gi);
            cp16(sa + SO_QLO + off, g_qlo + gi);
        }
#pragma unroll
        for (int it = 0; it < 5; it++) {    // K rows 0..159
            int idx = t + it * 256;
            int row = idx >> 3, c8 = idx & 7;
            int kg  = q0 - WIN + row;
            bool ok = (kg >= 0) && (kg < L_);
            size_t gi = base + (size_t)(ok ? kg : 0) * E_ + ec + c8 * 8;
            uint32_t off = (uint32_t)(row * (STRH * 2) + c8 * 16);
            cp16z(sa + SO_KHI + off, g_khi + gi, ok);
            cp16z(sa + SO_KLO + off, g_klo + gi, ok);
        }
    };
    auto load_v = [&](int ec, int stg) {
        const uint32_t sa = sb + (uint32_t)stg * ASTG;
#pragma unroll
        for (int it = 0; it < 5; it++) {    // V rows 0..159 (pad zeroed once)
            int idx = t + it * 256;
            int row = idx >> 3, c8 = idx & 7;
            int kg  = q0 - WIN + row;
            bool ok = (kg >= 0) && (kg < L_);
            size_t gi = base + (size_t)(ok ? kg : 0) * E_ + ec + c8 * 8;
            uint32_t off = (uint32_t)(row * (STRH * 2) + c8 * 16);
            cp16z(sa + SO_KHI + off, g_vhi + gi, ok);
            cp16z(sa + SO_KLO + off, g_vlo + gi, ok);
        }
    };

    // ---------------- Phase 1: S = Q K^T (pipelined over 8 e-chunks) -------
    float acc[2][3][4];
#pragma unroll
    for (int mi = 0; mi < 2; mi++)
#pragma unroll
        for (int nj = 0; nj < 3; nj++)
#pragma unroll
            for (int r = 0; r < 4; r++) acc[mi][nj][r] = 0.f;

    load_qk(0, 0);
    CP_COMMIT();

    for (int ci = 0; ci < 8; ci++) {
        const int stg = ci & 1;
        if (ci < 7) {
            load_qk((ci + 1) * ACH, stg ^ 1);
            CP_COMMIT();
            CP_WAIT(1);
        } else {
            CP_WAIT(0);
        }
        __syncthreads();

        const uint32_t sa = sb + (uint32_t)stg * ASTG;
#pragma unroll
        for (int kk = 0; kk < 4; kk++) {
            const uint32_t kOff = (uint32_t)(kk * 32);
            uint32_t aH[2][4], aL[2][4];
#pragma unroll
            for (int mi = 0; mi < 2; mi++) {
                uint32_t rowOff = (uint32_t)(mi * 16 * (STRH * 2));
                ldsm_x4(aH[mi], sa + SO_QHI + rowOff + kOff + aOff);
                ldsm_x4(aL[mi], sa + SO_QLO + rowOff + kOff + aOff);
            }
            const uint32_t nb0 = (uint32_t)(wid * 24 * (STRH * 2));
            const uint32_t nb1 = (uint32_t)((wid * 24 + 16) * (STRH * 2));
            uint32_t bH0[4], bH1[4], bL0[4], bL1[4];
            ldsm_x4(bH0, sa + SO_KHI + nb0 + kOff + bOff);
            ldsm_x4(bH1, sa + SO_KHI + nb1 + kOff + bOff);
            ldsm_x4(bL0, sa + SO_KLO + nb0 + kOff + bOff);
            ldsm_x4(bL1, sa + SO_KLO + nb1 + kOff + bOff);
#pragma unroll
            for (int mi = 0; mi < 2; mi++)
#pragma unroll
                for (int nj = 0; nj < 3; nj++) {
                    uint32_t h0 = (nj < 2) ? bH0[nj * 2]     : bH1[0];
                    uint32_t h1 = (nj < 2) ? bH0[nj * 2 + 1] : bH1[1];
                    uint32_t l0 = (nj < 2) ? bL0[nj * 2]     : bL1[0];
                    uint32_t l1 = (nj < 2) ? bL0[nj * 2 + 1] : bL1[1];
                    mma16816(acc[mi][nj], aH[mi], h0, h1);
                    mma16816(acc[mi][nj], aH[mi], l0, l1);
                    mma16816(acc[mi][nj], aL[mi], h0, h1);
                }
        }
        __syncthreads();
    }

    // write scores (n < 160 only) to fp32 smem
    {
        const int rA = lid >> 2, cA = (lid & 3) * 2;
#pragma unroll
        for (int mi = 0; mi < 2; mi++)
#pragma unroll
            for (int nj = 0; nj < 3; nj++) {
                int n = wid * 24 + nj * 8 + cA;
                if (n < NR) {
                    int r0 = mi * 16 + rA;
                    scS[r0 * SSTA + n]           = acc[mi][nj][0];
                    scS[r0 * SSTA + n + 1]       = acc[mi][nj][1];
                    scS[(r0 + 8) * SSTA + n]     = acc[mi][nj][2];
                    scS[(r0 + 8) * SSTA + n + 1] = acc[mi][nj][3];
                }
            }
    }

    // prefetch V chunk 0 into stage 0 while softmax runs
    load_v(0, 0);
    CP_COMMIT();

    // zero the pad rows (160..191) of BOTH stages once: 4 uint4 per thread
    {
        uint4 zz = make_uint4(0, 0, 0, 0);
#pragma unroll
        for (int s = 0; s < 2; s++) {
            int idx = t;                    // 256 threads cover 32 rows x 8 c8
            int row = NR + (idx >> 3), c8 = idx & 7;
            uint32_t off = (uint32_t)(row * (STRH * 2) + c8 * 16);
            char* sa = smem + s * ASTG;
            *(uint4*)(sa + SO_KHI + off) = zz;
            *(uint4*)(sa + SO_KLO + off) = zz;
        }
    }
    __syncthreads();

    // ---------------- Softmax (fp32), emit P as split bf16 ------------------
    {
        const float inv_sqrt_e = 0.04419417382415922f;  // 1/sqrt(512)
        const int qi  = t >> 3;
        const int sub = t & 7;
        float vals[20];
        float m = -INFINITY;
#pragma unroll
        for (int u = 0; u < 20; u++) {
            int r  = sub * 20 + u;
            int wj = r - qi;
            int kg = q0 + r - WIN;
            bool valid = (wj >= 0) && (wj <= 2 * WIN) && (kg >= 0) && (kg < L_);
            float s = valid ? scS[qi * SSTA + r] * inv_sqrt_e : -INFINITY;
            vals[u] = s;
            m = fmaxf(m, s);
        }
#pragma unroll
        for (int o = 1; o < 8; o <<= 1)
            m = fmaxf(m, __shfl_xor_sync(0xffffffffu, m, o, 8));
        float ssum = 0.f;
#pragma unroll
        for (int u = 0; u < 20; u++) {
            float e = (vals[u] == -INFINITY) ? 0.f : __expf(vals[u] - m);
            vals[u] = e;
            ssum += e;
        }
#pragma unroll
        for (int o = 1; o < 8; o <<= 1)
            ssum += __shfl_xor_sync(0xffffffffu, ssum, o, 8);
        float inv = 1.f / ssum;

        __nv_bfloat16* phi = (__nv_bfloat16*)(smem + O_PHI);
        __nv_bfloat16* plo = (__nv_bfloat16*)(smem + O_PLO);
#pragma unroll
        for (int u = 0; u < 20; u++) {
            float p = vals[u] * inv;
            __nv_bfloat16 h = __float2bfloat16(p);
            __nv_bfloat16 l = __float2bfloat16(p - __bfloat162float(h));
            phi[qi * PSTR + sub * 20 + u] = h;
            plo[qi * PSTR + sub * 20 + u] = l;
        }
        // zero pad columns 160..191 (k-dim padding for phase 2)
        __nv_bfloat16 z = __float2bfloat16(0.0f);
#pragma unroll
        for (int u = 0; u < 4; u++) {
            int r = NR + sub * 4 + u;
            phi[qi * PSTR + r] = z;
            plo[qi * PSTR + r] = z;
        }
    }
    __syncthreads();

    // ---------------- Phase 2: out = P @ V (pipelined over 8 e-chunks) -----
    float* gout = out + base;
    for (int ci = 0; ci < 8; ci++) {
        const int stg = ci & 1;
        if (ci < 7) {
            load_v((ci + 1) * ACH, stg ^ 1);
            CP_COMMIT();
            CP_WAIT(1);
        } else {
            CP_WAIT(0);
        }
        __syncthreads();

        const uint32_t sa = sb + (uint32_t)stg * ASTG;
        float o[2][4];
#pragma unroll
        for (int mi = 0; mi < 2; mi++)
#pragma unroll
            for (int r = 0; r < 4; r++) o[mi][r] = 0.f;

#pragma unroll
        for (int ks = 0; ks < 6; ks++) {   // k32 per iteration (192 total)
            uint32_t vrow = (uint32_t)((ks * 32 + lid) * (STRH * 2) + wid * 16);
            uint32_t vH[4], vL[4];
            ldsm_x4_t(vH, sa + SO_KHI + vrow);
            ldsm_x4_t(vL, sa + SO_KLO + vrow);
#pragma unroll
            for (int half = 0; half < 2; half++) {
                uint32_t kOff = (uint32_t)((ks * 32 + half * 16) * 2);
                uint32_t aH[2][4], aL[2][4];
#pragma unroll
                for (int mi = 0; mi < 2; mi++) {
                    uint32_t rowOff = (uint32_t)(mi * 16 * (PSTR * 2));
                    ldsm_x4(aH[mi], sb + O_PHI + rowOff + kOff + aPOff);
                    ldsm_x4(aL[mi], sb + O_PLO + rowOff + kOff + aPOff);
                }
                uint32_t h0 = vH[half * 2], h1 = vH[half * 2 + 1];
                uint32_t l0 = vL[half * 2], l1 = vL[half * 2 + 1];
#pragma unroll
                for (int mi = 0; mi < 2; mi++) {
                    mma16816(o[mi], aH[mi], h0, h1);   // Phi*Vhi
                    mma16816(o[mi], aH[mi], l0, l1);   // Phi*Vlo
                    mma16816(o[mi], aL[mi], h0, h1);   // Plo*Vhi
                }
            }
        }

        {   // store fp32 output
            int col = ci * ACH + wid * 8 + (lid & 3) * 2;
#pragma unroll
            for (int mi = 0; mi < 2; mi++) {
                int r = q0 + mi * 16 + (lid >> 2);
                *(float2*)&gout[(size_t)r * E_ + col] =
                    make_float2(o[mi][0], o[mi][1]);
                *(float2*)&gout[(size_t)(r + 8) * E_ + col] =
                    make_float2(o[mi][2], o[mi][3]);
            }
        }
        __syncthreads();
    }
}

// ============================================================================
extern "C" void kernel_launch(void* const* d_in, const int* in_sizes, int n_in,
                              void* d_out, int out_size)
{
    const float* x  = (const float*)d_in[0];
    const float* Wq = (const float*)d_in[1];
    const float* bq = (const float*)d_in[2];
    const float* Wk = (const float*)d_in[3];
    const float* bk = (const float*)d_in[4];
    const float* Wv = (const float*)d_in[5];
    const float* bv = (const float*)d_in[6];
    float* out = (float*)d_out;

    // 1) split X / W into bf16 hi/lo
    split_all<<<dim3(512, 4), 256>>>(x, Wq, Wk, Wv);

    // 2) QKV projections on tensor cores -> split bf16 q/k/v
    cudaFuncSetAttribute(qkv_tc, cudaFuncAttributeMaxDynamicSharedMemorySize,
                         QT_SMEM);
    dim3 ggrid((B_ * L_) / 128, E_ / 128, 3);
    qkv_tc<<<ggrid, 256, QT_SMEM>>>(bq, bk, bv);

    // 3) banded attention on tensor cores
    cudaFuncSetAttribute(attn_tc, cudaFuncAttributeMaxDynamicSharedMemorySize,
                         A_SMEM);
    dim3 agrid(L_ / TQ, B_);
    attn_tc<<<agrid, 256, A_SMEM>>>(out);
}